// round 12
// baseline (speedup 1.0000x reference)
#include <cuda_runtime.h>
#include <cuda_fp16.h>
#include <math.h>
#include <cstdint>

#define Bz 128
#define Lz 128
#define HEz 1024
#define HDz 1024
#define Ez 512
#define APz 512
#define Tz 64
#define K1z 2560        // [x_t | a_t | h1_prev]
#define K2z 2048        // [h1 | h2]
#define N2z 5120        // gates2 (4096) + out-proj (1024)

// ---------------- device scratch ----------------
__device__ __align__(128) __half g_enc_proj[Bz * Lz * APz];
__device__ __align__(128) __half g_ehtf[Bz * Lz * HEz];
__device__ __align__(128) float  g_q[Bz * APz];
__device__ __align__(128) float  g_e[Bz * Lz];
__device__ __align__(128) __half g_abuf1[Bz * K1z];
__device__ __align__(128) __half g_abuf2[Bz * K2z];
__device__ __align__(128) float  g_gates1[Bz * 4 * HDz];
__device__ __align__(128) float  g_g2c[Bz * N2z];
__device__ __align__(128) float  g_c1[Bz * HDz];
__device__ __align__(128) float  g_c2[Bz * HDz];
__device__ __align__(128) __half g_hprev[Bz * HDz];
__device__ __align__(128) __half g_W1t[4 * HDz * K1z];
__device__ __align__(128) __half g_W2c[N2z * K2z];
__device__ __align__(128) __half g_dhpWt[APz * HDz];
__device__ __align__(128) __half g_attWt[APz * HEz];
__device__ __align__(128) float  g_gb1[4 * HDz];
__device__ __align__(128) float  g_gb2c[N2z];

__device__ __forceinline__ float fast_tanh(float x) {
    float y; asm("tanh.approx.f32 %0, %1;" : "=f"(y) : "f"(x)); return y;
}
__device__ __forceinline__ float sigmoidf_(float x) { return 1.0f / (1.0f + expf(-x)); }
__device__ __forceinline__ uint32_t smem_u32(const void* p) {
    uint32_t a;
    asm("{ .reg .u64 t; cvta.to.shared.u64 t, %1; cvt.u32.u64 %0, t; }" : "=r"(a) : "l"(p));
    return a;
}
#define CP16(dst, src) \
    asm volatile("cp.async.cg.shared.global [%0], [%1], 16;" :: "r"(dst), "l"(src))
#define LDSM4(d0, d1, d2, d3, addr) \
    asm volatile("ldmatrix.sync.aligned.m8n8.x4.shared.b16 {%0,%1,%2,%3}, [%4];" \
                 : "=r"(d0), "=r"(d1), "=r"(d2), "=r"(d3) : "r"(addr))
// PDL
#define GRID_WAIT()       asm volatile("griddepcontrol.wait;" ::: "memory")
#define GRID_LAUNCH_DEP() asm volatile("griddepcontrol.launch_dependents;" ::: "memory")

// ---------------- 3-stage pipelined HMMA fp16 GEMM (m16n8k16 + ldmatrix + PDL) --
#define BMt 64
#define BN 128
#define BKh 64
#define SWH 72
#define STGH ((BMt + BN) * SWH)

__global__ __launch_bounds__(256, 2) void gemm_mma(
    const __half* __restrict__ A, int lda,
    const __half* __restrict__ Bt, int ldb,
    float* __restrict__ C, int ldc,
    int chunk, const float* __restrict__ bias, int flags)
{
    extern __shared__ __half smh[];
    const int tid = threadIdx.x;
    const int wid = tid >> 5, lane = tid & 31;
    const int wm = wid & 1, wn = wid >> 1;
    const int lrow = lane >> 2, lcol = lane & 3;
    const int n0 = blockIdx.x * BN;
    const int m0 = blockIdx.y * BMt;
    const int kbeg = blockIdx.z * chunk;
    const int NC = chunk / BKh;

    float c[2][4][4];
    #pragma unroll
    for (int i = 0; i < 2; i++)
        #pragma unroll
        for (int j = 0; j < 4; j++)
            #pragma unroll
            for (int r = 0; r < 4; r++) c[i][j][r] = 0.0f;

    const uint32_t sbase = smem_u32(smh);
    const __half* Abase = A + (size_t)m0 * lda + kbeg;
    const __half* Bbase = Bt + (size_t)n0 * ldb + kbeg;

    const int ar0 = (tid + 0)   >> 3, ao0 = (tid + 0)   & 7;
    const int ar1 = (tid + 256) >> 3, ao1 = (tid + 256) & 7;

    const uint32_t a_off =
        ((uint32_t)((wm * 32 + (lane & 15)) * SWH + ((lane >> 4) << 3))) * 2;
    const uint32_t b_off =
        ((uint32_t)((BMt + wn * 32 + (lane & 7) + (((lane >> 4) & 1) << 3)) * SWH
                    + (((lane >> 3) & 1) << 3))) * 2;

#define LOAD_A_STAGE(ck, st) do {                                                 \
        uint32_t sb = sbase + (uint32_t)(st) * STGH * 2;                          \
        const __half* Ag = Abase + (size_t)(ck) * BKh;                            \
        CP16(sb + ar0 * 144 + ao0 * 16, Ag + (size_t)ar0 * lda + ao0 * 8);        \
        CP16(sb + ar1 * 144 + ao1 * 16, Ag + (size_t)ar1 * lda + ao1 * 8);        \
    } while (0)
#define LOAD_B_STAGE(ck, st) do {                                                 \
        uint32_t sb = sbase + (uint32_t)(st) * STGH * 2;                          \
        const __half* Bg = Bbase + (size_t)(ck) * BKh;                            \
        _Pragma("unroll")                                                         \
        for (int j = 0; j < 4; j++) {                                             \
            int i = tid + j * 256;                                                \
            int row = i >> 3, off = i & 7;                                        \
            CP16(sb + (BMt + row) * 144 + off * 16,                               \
                 Bg + (size_t)row * ldb + off * 8);                               \
        }                                                                         \
    } while (0)

    // weight prefetch (independent of predecessor) BEFORE the PDL wait
    LOAD_B_STAGE(0, 0);
    if (NC > 1) LOAD_B_STAGE(1, 1);
    GRID_WAIT();
    LOAD_A_STAGE(0, 0);
    asm volatile("cp.async.commit_group;" ::: "memory");
    if (NC > 1) {
        LOAD_A_STAGE(1, 1);
        asm volatile("cp.async.commit_group;" ::: "memory");
    }

    int s = 0;
    for (int cc = 0; cc < NC; cc++) {
        if (cc + 1 < NC) { asm volatile("cp.async.wait_group 1;" ::: "memory"); }
        else             { asm volatile("cp.async.wait_group 0;" ::: "memory"); }
        __syncthreads();
        if (cc + 2 < NC) {
            int st = s + 2 >= 3 ? s - 1 : s + 2;
            LOAD_B_STAGE(cc + 2, st);
            LOAD_A_STAGE(cc + 2, st);
            asm volatile("cp.async.commit_group;" ::: "memory");
        }

        const uint32_t stg = sbase + (uint32_t)s * STGH * 2;
        const uint32_t aad = stg + a_off;
        const uint32_t bad = stg + b_off;

        #pragma unroll
        for (int ks = 0; ks < 4; ks++) {
            uint32_t a[2][4], b[4][2];
            const uint32_t kso = ks * 32;
            LDSM4(a[0][0], a[0][1], a[0][2], a[0][3], aad + kso);
            LDSM4(a[1][0], a[1][1], a[1][2], a[1][3], aad + 16 * SWH * 2 + kso);
            LDSM4(b[0][0], b[0][1], b[1][0], b[1][1], bad + kso);
            LDSM4(b[2][0], b[2][1], b[3][0], b[3][1], bad + 16 * SWH * 2 + kso);
            #pragma unroll
            for (int mi = 0; mi < 2; mi++)
                #pragma unroll
                for (int nj = 0; nj < 4; nj++)
                    asm volatile(
                        "mma.sync.aligned.m16n8k16.row.col.f32.f16.f16.f32 "
                        "{%0,%1,%2,%3}, {%4,%5,%6,%7}, {%8,%9}, {%0,%1,%2,%3};"
                        : "+f"(c[mi][nj][0]), "+f"(c[mi][nj][1]),
                          "+f"(c[mi][nj][2]), "+f"(c[mi][nj][3])
                        : "r"(a[mi][0]), "r"(a[mi][1]), "r"(a[mi][2]), "r"(a[mi][3]),
                          "r"(b[nj][0]), "r"(b[nj][1]));
        }
        s = (s + 1 == 3) ? 0 : s + 1;
    }
#undef LOAD_A_STAGE
#undef LOAD_B_STAGE

    GRID_LAUNCH_DEP();

    const bool single = (gridDim.z == 1);
    const bool addb = (blockIdx.z == 0);
    const bool h16 = (flags & 1);
    #pragma unroll
    for (int mi = 0; mi < 2; mi++) {
        const int row = m0 + wm * 32 + mi * 16 + lrow;
        #pragma unroll
        for (int nj = 0; nj < 4; nj++) {
            const int col = n0 + wn * 32 + nj * 8 + 2 * lcol;
            float b0 = addb ? bias[col] : 0.0f;
            float b1 = addb ? bias[col + 1] : 0.0f;
            if (single) {
                if (h16) {
                    __half* Ch = (__half*)C;
                    *(__half2*)(Ch + (size_t)row * ldc + col) =
                        __floats2half2_rn(c[mi][nj][0] + b0, c[mi][nj][1] + b1);
                    *(__half2*)(Ch + (size_t)(row + 8) * ldc + col) =
                        __floats2half2_rn(c[mi][nj][2] + b0, c[mi][nj][3] + b1);
                } else {
                    *(float2*)&C[(size_t)row * ldc + col] =
                        make_float2(c[mi][nj][0] + b0, c[mi][nj][1] + b1);
                    *(float2*)&C[(size_t)(row + 8) * ldc + col] =
                        make_float2(c[mi][nj][2] + b0, c[mi][nj][3] + b1);
                }
            } else {
                atomicAdd(&C[(size_t)row * ldc + col],           c[mi][nj][0] + b0);
                atomicAdd(&C[(size_t)row * ldc + col + 1],       c[mi][nj][1] + b1);
                atomicAdd(&C[(size_t)(row + 8) * ldc + col],     c[mi][nj][2] + b0);
                atomicAdd(&C[(size_t)(row + 8) * ldc + col + 1], c[mi][nj][3] + b1);
            }
        }
    }
}

// ---------------- merged one-time prep ----------------
#define PJ0 512
#define PJ1 1024
#define PJ2 7168
#define PJ3 11264
#define PJ4 15360
#define PJ5 19456
#define PJ6 20480
#define PJ7 21504
#define PJ8 21520
#define PJ9 22032
#define PJTOT 38416

__global__ __launch_bounds__(256) void prep_all(
    const float* __restrict__ att_W, const float* __restrict__ dhp_W,
    const float* __restrict__ W_ih1, const float* __restrict__ W_hh1,
    const float* __restrict__ W_ih2, const float* __restrict__ W_hh2,
    const float* __restrict__ lt_W,
    const float* __restrict__ b_ih1, const float* __restrict__ b_hh1,
    const float* __restrict__ b_ih2, const float* __restrict__ b_hh2,
    const float* __restrict__ lt_b,
    const float* __restrict__ h1_0, const float* __restrict__ c1_0,
    const float* __restrict__ h2_0, const float* __restrict__ c2_0,
    const float* __restrict__ enc_hiddens)
{
    __shared__ float tile[32][33];
    const int bid = blockIdx.x;
    const int tid = threadIdx.x;
    const int tx = tid & 31, ty = tid >> 5;

#define DO_TR(src, K, N, dst, ldd, koff, tIdx) do {                                \
        int nkb = (K) >> 5;                                                        \
        int kb = ((tIdx) % nkb) * 32, nb = ((tIdx) / nkb) * 32;                    \
        _Pragma("unroll")                                                          \
        for (int i = ty; i < 32; i += 8)                                           \
            tile[i][tx] = (src)[(size_t)(kb + i) * (N) + nb + tx];                 \
        __syncthreads();                                                           \
        _Pragma("unroll")                                                          \
        for (int i = ty; i < 32; i += 8)                                           \
            (dst)[(size_t)(nb + i) * (ldd) + (koff) + kb + tx] =                   \
                __float2half_rn(tile[tx][i]);                                      \
    } while (0)

    if (bid < PJ0) {
        DO_TR(att_W, HEz, APz, g_attWt, HEz, 0, bid);
    } else if (bid < PJ1) {
        DO_TR(dhp_W, HDz, APz, g_dhpWt, HDz, 0, bid - PJ0);
    } else if (bid < PJ2) {
        DO_TR(W_ih1, 1536, 4 * HDz, g_W1t, K1z, 0, bid - PJ1);
    } else if (bid < PJ3) {
        DO_TR(W_hh1, HDz, 4 * HDz, g_W1t, K1z, 1536, bid - PJ2);
    } else if (bid < PJ4) {
        DO_TR(W_ih2, HDz, 4 * HDz, g_W2c, K2z, 0, bid - PJ3);
    } else if (bid < PJ5) {
        DO_TR(W_hh2, HDz, 4 * HDz, g_W2c, K2z, 1024, bid - PJ4);
    } else if (bid < PJ6) {
        DO_TR(lt_W, HDz, HDz, g_W2c + (size_t)4 * HDz * K2z, K2z, 0, bid - PJ5);
    } else if (bid < PJ7) {
        int row = 4 * HDz + (bid - PJ6);
        __half z = __float2half(0.0f);
        #pragma unroll
        for (int j = 0; j < 4; j++)
            g_W2c[(size_t)row * K2z + 1024 + tid * 4 + j] = z;
    } else if (bid < PJ8) {
        int i = (bid - PJ7) * 256 + tid;
        g_gb1[i]  = b_ih1[i] + b_hh1[i];
        g_gb2c[i] = b_ih2[i] + b_hh2[i];
        if (i < HDz) g_gb2c[4 * HDz + i] = lt_b[i];
    } else if (bid < PJ9) {
        int idx = (bid - PJ8) * 256 + tid;
        int b = idx >> 10, j = idx & (HDz - 1);
        g_c1[idx] = c1_0[idx];
        g_c2[idx] = c2_0[idx];
        g_abuf1[(size_t)b * K1z + 1536 + j] = __float2half_rn(h1_0[idx]);
        g_abuf2[(size_t)b * K2z + 1024 + j] = __float2half_rn(h2_0[idx]);
        g_hprev[idx] = __float2half_rn(1.0f / (float)HEz);
        #pragma unroll
        for (int gi = 0; gi < 4; gi++)
            g_gates1[(size_t)b * 4 * HDz + gi * HDz + j] = 0.0f;
        if (idx < Bz * APz) g_q[idx] = 0.0f;
    } else {
        size_t i = (size_t)(bid - PJ9) * 256 + tid;
        float4 v = *(const float4*)(enc_hiddens + i * 4);
        __half2* d = (__half2*)g_ehtf;
        d[2 * i]     = __floats2half2_rn(v.x, v.y);
        d[2 * i + 1] = __floats2half2_rn(v.z, v.w);
    }
#undef DO_TR
}

// ---------------- attention logits (PDL): grid (B, 4) x 256 ----------------
__global__ __launch_bounds__(256) void attn_e(
    const int* __restrict__ enc_masks,
    const float* __restrict__ corr_w, const float* __restrict__ corr_b,
    const float* __restrict__ captions, int t)
{
    __shared__ __align__(16) float qv[APz];
    __shared__ __align__(16) float cw[APz];
    const int b = blockIdx.x, yc = blockIdx.y;
    const int tid = threadIdx.x, lane = tid & 31, warp = tid >> 5;

    // pre-wait work: corr_w + x_t copy (independent of predecessor)
    for (int i = tid; i < APz; i += 256) cw[i] = corr_w[i];
    if (tid < 128) {
        int ci = yc * 128 + tid;
        g_abuf1[(size_t)b * K1z + ci] =
            __float2half_rn(captions[((size_t)t * Bz + b) * Ez + ci]);
    }
    GRID_WAIT();
    for (int i = tid; i < APz; i += 256) qv[i] = g_q[b * APz + i];
    __syncthreads();

    const float cb = corr_b[0];
    #pragma unroll
    for (int li = 0; li < 4; li++) {
        const int l = yc * 32 + warp + li * 8;
        const uint4* ep = (const uint4*)(g_enc_proj + ((size_t)(b * Lz + l)) * APz);
        float acc = 0.0f;
        #pragma unroll
        for (int u = 0; u < 2; u++) {
            uint4 pk = ep[lane * 2 + u];
            const __half2* h2 = (const __half2*)&pk;
            const int ap0 = lane * 16 + u * 8;
            #pragma unroll
            for (int p = 0; p < 4; p++) {
                float2 v = __half22float2(h2[p]);
                acc += fast_tanh(v.x + qv[ap0 + 2 * p]) * cw[ap0 + 2 * p];
                acc += fast_tanh(v.y + qv[ap0 + 2 * p + 1]) * cw[ap0 + 2 * p + 1];
            }
        }
        #pragma unroll
        for (int off = 16; off; off >>= 1) acc += __shfl_xor_sync(0xffffffffu, acc, off);
        if (lane == 0) {
            float v = acc + cb;
            if (enc_masks[b * Lz + l]) v = -INFINITY;
            g_e[b * Lz + l] = v;
        }
    }
    GRID_LAUNCH_DEP();
}

// ---------------- attention weighted sum (PDL): grid (B, 4) x 128 --------------
__global__ __launch_bounds__(128) void attn_at()
{
    __shared__ float al[Lz];
    const int b = blockIdx.x, hc = blockIdx.y;
    const int tid = threadIdx.x;

    GRID_WAIT();
    if (tid < Lz) al[tid] = g_e[b * Lz + tid];
    __syncthreads();
    if (tid < 32) {
        float m = -INFINITY;
        #pragma unroll
        for (int i = 0; i < 4; i++) m = fmaxf(m, al[tid + 32 * i]);
        #pragma unroll
        for (int off = 16; off; off >>= 1) m = fmaxf(m, __shfl_xor_sync(0xffffffffu, m, off));
        float ex[4], s = 0.0f;
        #pragma unroll
        for (int i = 0; i < 4; i++) { ex[i] = __expf(al[tid + 32 * i] - m); s += ex[i]; }
        #pragma unroll
        for (int off = 16; off; off >>= 1) s += __shfl_xor_sync(0xffffffffu, s, off);
        float inv = 1.0f / s;
        #pragma unroll
        for (int i = 0; i < 4; i++) al[tid + 32 * i] = ex[i] * inv;
    }
    __syncthreads();

    // half2 column index: 128 per block chunk
    const int h2i = hc * 128 + tid;
    const __half2* eh2 = (const __half2*)(g_ehtf + (size_t)b * Lz * HEz);
    float2 acc2 = make_float2(0.0f, 0.0f);
    #pragma unroll 8
    for (int l = 0; l < Lz; l++) {
        float2 v = __half22float2(eh2[(size_t)l * (HEz / 2) + h2i]);
        float a = al[l];
        acc2.x += a * v.x;
        acc2.y += a * v.y;
    }
    *(__half2*)(g_abuf1 + (size_t)b * K1z + Ez + 2 * h2i) =
        __floats2half2_rn(acc2.x, acc2.y);
    GRID_LAUNCH_DEP();
}

// ---------------- LSTM pointwise (PDL) ----------------
__global__ __launch_bounds__(256) void lstm_point1()
{
    GRID_WAIT();
    int idx = blockIdx.x * blockDim.x + threadIdx.x;
    int b = idx >> 10, j = idx & (HDz - 1);
    const float* g = g_gates1 + (size_t)b * 4 * HDz;
    float ig = sigmoidf_(g[j]);
    float fg = sigmoidf_(g[HDz + j]);
    float gg = tanhf(g[2 * HDz + j]);
    float og = sigmoidf_(g[3 * HDz + j]);
    float cn = fg * g_c1[idx] + ig * gg;
    float hn = og * tanhf(cn);
    GRID_LAUNCH_DEP();
    g_c1[idx] = cn;
    __half hn_h = __float2half_rn(hn);
    g_abuf2[(size_t)b * K2z + j] = hn_h;
    g_abuf1[(size_t)b * K1z + 1536 + j] = hn_h;
    #pragma unroll
    for (int gi = 0; gi < 5; gi++)
        g_g2c[(size_t)b * N2z + gi * HDz + j] = 0.0f;
}

__global__ __launch_bounds__(256) void lstm_point2(float* __restrict__ out)
{
    GRID_WAIT();
    int idx = blockIdx.x * blockDim.x + threadIdx.x;
    int b = idx >> 10, j = idx & (HDz - 1);
    const float* g = g_g2c + (size_t)b * N2z;
    float ig = sigmoidf_(g[j]);
    float fg = sigmoidf_(g[HDz + j]);
    float gg = tanhf(g[2 * HDz + j]);
    float og = sigmoidf_(g[3 * HDz + j]);
    float cn = fg * g_c2[idx] + ig * gg;
    float hn = og * tanhf(cn);
    GRID_LAUNCH_DEP();
    g_c2[idx] = cn;
    __half hn_h = __float2half_rn(hn);
    g_abuf2[(size_t)b * K2z + 1024 + j] = hn_h;
    g_hprev[idx] = hn_h;
    out[idx] = tanhf(g[4 * HDz + j]);
    #pragma unroll
    for (int gi = 0; gi < 4; gi++)
        g_gates1[(size_t)b * 4 * HDz + gi * HDz + j] = 0.0f;
    if (idx < Bz * APz) g_q[idx] = 0.0f;
}

// ---------------- PDL launch helper ----------------
template <class T> struct idt { using type = T; };
template <typename... Args>
static inline void launch_pdl(dim3 grid, dim3 block, size_t shm,
                              void (*kern)(Args...),
                              typename idt<Args>::type... args)
{
    cudaLaunchConfig_t cfg = {};
    cfg.gridDim = grid; cfg.blockDim = block;
    cfg.dynamicSmemBytes = shm; cfg.stream = 0;
    cudaLaunchAttribute at[1];
    at[0].id = cudaLaunchAttributeProgrammaticStreamSerialization;
    at[0].val.programmaticStreamSerializationAllowed = 1;
    cfg.attrs = at; cfg.numAttrs = 1;
    cudaLaunchKernelEx(&cfg, kern, args...);
}

// ---------------- host launcher ----------------
extern "C" void kernel_launch(void* const* d_in, const int* in_sizes, int n_in,
                              void* d_out, int out_size)
{
    const float* enc_hiddens = (const float*)d_in[0];
    const int*   enc_masks   = (const int*)  d_in[1];
    const float* h1_0 = (const float*)d_in[2];
    const float* c1_0 = (const float*)d_in[3];
    const float* h2_0 = (const float*)d_in[4];
    const float* c2_0 = (const float*)d_in[5];
    const float* captions = (const float*)d_in[6];
    const float* att_W = (const float*)d_in[7];
    const float* att_b = (const float*)d_in[8];
    const float* dhp_W = (const float*)d_in[9];
    const float* dhp_b = (const float*)d_in[10];
    const float* corr_w = (const float*)d_in[11];
    const float* corr_b = (const float*)d_in[12];
    const float* lt_W = (const float*)d_in[13];
    const float* lt_b = (const float*)d_in[14];
    const float* W_ih1 = (const float*)d_in[15];
    const float* W_hh1 = (const float*)d_in[16];
    const float* b_ih1 = (const float*)d_in[17];
    const float* b_hh1 = (const float*)d_in[18];
    const float* W_ih2 = (const float*)d_in[19];
    const float* W_hh2 = (const float*)d_in[20];
    const float* b_ih2 = (const float*)d_in[21];
    const float* b_hh2 = (const float*)d_in[22];
    float* out = (float*)d_out;

    static bool inited = false;
    static __half *p_enc_proj, *p_ehtf, *p_a1, *p_a2, *p_hprev;
    static __half *p_W1t, *p_W2c, *p_dhpWt, *p_attWt;
    static float *p_g1, *p_g2c, *p_q, *p_gb1, *p_gb2c;
    if (!inited) {
        cudaGetSymbolAddress((void**)&p_enc_proj, g_enc_proj);
        cudaGetSymbolAddress((void**)&p_ehtf,  g_ehtf);
        cudaGetSymbolAddress((void**)&p_a1,    g_abuf1);
        cudaGetSymbolAddress((void**)&p_a2,    g_abuf2);
        cudaGetSymbolAddress((void**)&p_g1,    g_gates1);
        cudaGetSymbolAddress((void**)&p_g2c,   g_g2c);
        cudaGetSymbolAddress((void**)&p_q,     g_q);
        cudaGetSymbolAddress((void**)&p_hprev, g_hprev);
        cudaGetSymbolAddress((void**)&p_W1t,   g_W1t);
        cudaGetSymbolAddress((void**)&p_W2c,   g_W2c);
        cudaGetSymbolAddress((void**)&p_dhpWt, g_dhpWt);
        cudaGetSymbolAddress((void**)&p_attWt, g_attWt);
        cudaGetSymbolAddress((void**)&p_gb1,   g_gb1);
        cudaGetSymbolAddress((void**)&p_gb2c,  g_gb2c);
        cudaFuncSetAttribute(gemm_mma, cudaFuncAttributeMaxDynamicSharedMemorySize,
                             3 * STGH * 2);
        inited = true;
    }
    const int GSM = 3 * STGH * 2;   // 82944 B

    prep_all<<<PJTOT, 256>>>(att_W, dhp_W, W_ih1, W_hh1, W_ih2, W_hh2, lt_W,
                             b_ih1, b_hh1, b_ih2, b_hh2, lt_b,
                             h1_0, c1_0, h2_0, c2_0, enc_hiddens);

    gemm_mma<<<dim3(APz / BN, Bz * Lz / BMt, 1), 256, GSM>>>(
        p_ehtf, HEz, p_attWt, HEz, (float*)p_enc_proj, APz, HEz, att_b, 1);

    for (int t = 0; t < Tz; t++) {
        // q += hprev @ dhp_W (+dhp_b)   K=1024, z=16
        launch_pdl(dim3(APz / BN, Bz / BMt, 16), dim3(256), (size_t)GSM, gemm_mma,
                   (const __half*)p_hprev, HDz, (const __half*)p_dhpWt, HDz,
                   (float*)p_q, APz, 64, (const float*)dhp_b, 0);

        launch_pdl(dim3(Bz, 4), dim3(256), (size_t)0, attn_e,
                   enc_masks, corr_w, corr_b, captions, t);
        launch_pdl(dim3(Bz, 4), dim3(128), (size_t)0, attn_at);

        // gates1 += [x|a|h1] @ W1t^T (+gb1)   K=2560, z=4 -> 256 blocks
        launch_pdl(dim3(4 * HDz / BN, Bz / BMt, 4), dim3(256), (size_t)GSM, gemm_mma,
                   (const __half*)p_a1, K1z, (const __half*)p_W1t, K1z,
                   (float*)p_g1, 4 * HDz, 640, (const float*)p_gb1, 0);

        launch_pdl(dim3(Bz * HDz / 256), dim3(256), (size_t)0, lstm_point1);

        // [gates2 | outsc] += [h1|h2] @ W2c^T (+gb2c)   K=2048, z=4
        launch_pdl(dim3(N2z / BN, Bz / BMt, 4), dim3(256), (size_t)GSM, gemm_mma,
                   (const __half*)p_a2, K2z, (const __half*)p_W2c, K2z,
                   (float*)p_g2c, N2z, 512, (const float*)p_gb2c, 0);

        launch_pdl(dim3(Bz * HDz / 256), dim3(256), (size_t)0, lstm_point2,
                   (float*)(out + (size_t)t * Bz * HDz));
    }
    (void)in_sizes; (void)n_in; (void)out_size;
}

// round 13
// speedup vs baseline: 1.0450x; 1.0450x over previous
#include <cuda_runtime.h>
#include <cuda_fp16.h>
#include <math.h>
#include <cstdint>

#define Bz 128
#define Lz 128
#define HEz 1024
#define HDz 1024
#define Ez 512
#define APz 512
#define Tz 64
#define K1z 2560        // [x_t | a_t | h1_prev]
#define K2z 2048        // [h1 | h2]
#define N2z 5120        // gates2 (4096) + out-proj (1024)

// ---------------- device scratch ----------------
__device__ __align__(128) __half g_enc_proj[Bz * Lz * APz];
__device__ __align__(128) __half g_ehtf[Bz * Lz * HEz];
__device__ __align__(128) float  g_q[Bz * APz];
__device__ __align__(128) __half g_abuf1[Bz * K1z];
__device__ __align__(128) __half g_abuf2[Bz * K2z];
__device__ __align__(128) float  g_gates1[Bz * 4 * HDz];
__device__ __align__(128) float  g_g2c[Bz * N2z];
__device__ __align__(128) float  g_c1[Bz * HDz];
__device__ __align__(128) float  g_c2[Bz * HDz];
__device__ __align__(128) __half g_hprev[Bz * HDz];
__device__ __align__(128) __half g_W1t[4 * HDz * K1z];
__device__ __align__(128) __half g_W2c[N2z * K2z];
__device__ __align__(128) __half g_dhpWt[APz * HDz];
__device__ __align__(128) __half g_attWt[APz * HEz];
__device__ __align__(128) float  g_gb1[4 * HDz];
__device__ __align__(128) float  g_gb2c[N2z];

__device__ __forceinline__ float fast_tanh(float x) {
    float y; asm("tanh.approx.f32 %0, %1;" : "=f"(y) : "f"(x)); return y;
}
__device__ __forceinline__ float sigmoidf_(float x) { return 1.0f / (1.0f + expf(-x)); }
__device__ __forceinline__ uint32_t smem_u32(const void* p) {
    uint32_t a;
    asm("{ .reg .u64 t; cvta.to.shared.u64 t, %1; cvt.u32.u64 %0, t; }" : "=r"(a) : "l"(p));
    return a;
}
#define CP16(dst, src) \
    asm volatile("cp.async.cg.shared.global [%0], [%1], 16;" :: "r"(dst), "l"(src))
#define LDSM4(d0, d1, d2, d3, addr) \
    asm volatile("ldmatrix.sync.aligned.m8n8.x4.shared.b16 {%0,%1,%2,%3}, [%4];" \
                 : "=r"(d0), "=r"(d1), "=r"(d2), "=r"(d3) : "r"(addr))
// PDL
#define GRID_WAIT()       asm volatile("griddepcontrol.wait;" ::: "memory")
#define GRID_LAUNCH_DEP() asm volatile("griddepcontrol.launch_dependents;" ::: "memory")

// ---------------- 3-stage pipelined HMMA fp16 GEMM (m16n8k16 + ldmatrix + PDL) --
#define BMt 64
#define BN 128
#define BKh 64
#define SWH 72
#define STGH ((BMt + BN) * SWH)

__global__ __launch_bounds__(256, 2) void gemm_mma(
    const __half* __restrict__ A, int lda,
    const __half* __restrict__ Bt, int ldb,
    float* __restrict__ C, int ldc,
    int chunk, const float* __restrict__ bias, int flags)
{
    extern __shared__ __half smh[];
    const int tid = threadIdx.x;
    const int wid = tid >> 5, lane = tid & 31;
    const int wm = wid & 1, wn = wid >> 1;
    const int lrow = lane >> 2, lcol = lane & 3;
    const int n0 = blockIdx.x * BN;
    const int m0 = blockIdx.y * BMt;
    const int kbeg = blockIdx.z * chunk;
    const int NC = chunk / BKh;

    float c[2][4][4];
    #pragma unroll
    for (int i = 0; i < 2; i++)
        #pragma unroll
        for (int j = 0; j < 4; j++)
            #pragma unroll
            for (int r = 0; r < 4; r++) c[i][j][r] = 0.0f;

    const uint32_t sbase = smem_u32(smh);
    const __half* Abase = A + (size_t)m0 * lda + kbeg;
    const __half* Bbase = Bt + (size_t)n0 * ldb + kbeg;

    const int ar0 = (tid + 0)   >> 3, ao0 = (tid + 0)   & 7;
    const int ar1 = (tid + 256) >> 3, ao1 = (tid + 256) & 7;

    const uint32_t a_off =
        ((uint32_t)((wm * 32 + (lane & 15)) * SWH + ((lane >> 4) << 3))) * 2;
    const uint32_t b_off =
        ((uint32_t)((BMt + wn * 32 + (lane & 7) + (((lane >> 4) & 1) << 3)) * SWH
                    + (((lane >> 3) & 1) << 3))) * 2;

#define LOAD_A_STAGE(ck, st) do {                                                 \
        uint32_t sb = sbase + (uint32_t)(st) * STGH * 2;                          \
        const __half* Ag = Abase + (size_t)(ck) * BKh;                            \
        CP16(sb + ar0 * 144 + ao0 * 16, Ag + (size_t)ar0 * lda + ao0 * 8);        \
        CP16(sb + ar1 * 144 + ao1 * 16, Ag + (size_t)ar1 * lda + ao1 * 8);        \
    } while (0)
#define LOAD_B_STAGE(ck, st) do {                                                 \
        uint32_t sb = sbase + (uint32_t)(st) * STGH * 2;                          \
        const __half* Bg = Bbase + (size_t)(ck) * BKh;                            \
        _Pragma("unroll")                                                         \
        for (int j = 0; j < 4; j++) {                                             \
            int i = tid + j * 256;                                                \
            int row = i >> 3, off = i & 7;                                        \
            CP16(sb + (BMt + row) * 144 + off * 16,                               \
                 Bg + (size_t)row * ldb + off * 8);                               \
        }                                                                         \
    } while (0)

    // weight prefetch (independent of predecessor) BEFORE the PDL wait
    LOAD_B_STAGE(0, 0);
    if (NC > 1) LOAD_B_STAGE(1, 1);
    GRID_WAIT();
    LOAD_A_STAGE(0, 0);
    asm volatile("cp.async.commit_group;" ::: "memory");
    if (NC > 1) {
        LOAD_A_STAGE(1, 1);
        asm volatile("cp.async.commit_group;" ::: "memory");
    }

    int s = 0;
    for (int cc = 0; cc < NC; cc++) {
        if (cc + 1 < NC) { asm volatile("cp.async.wait_group 1;" ::: "memory"); }
        else             { asm volatile("cp.async.wait_group 0;" ::: "memory"); }
        __syncthreads();
        if (cc + 2 < NC) {
            int st = s + 2 >= 3 ? s - 1 : s + 2;
            LOAD_B_STAGE(cc + 2, st);
            LOAD_A_STAGE(cc + 2, st);
            asm volatile("cp.async.commit_group;" ::: "memory");
        }

        const uint32_t stg = sbase + (uint32_t)s * STGH * 2;
        const uint32_t aad = stg + a_off;
        const uint32_t bad = stg + b_off;

        #pragma unroll
        for (int ks = 0; ks < 4; ks++) {
            uint32_t a[2][4], b[4][2];
            const uint32_t kso = ks * 32;
            LDSM4(a[0][0], a[0][1], a[0][2], a[0][3], aad + kso);
            LDSM4(a[1][0], a[1][1], a[1][2], a[1][3], aad + 16 * SWH * 2 + kso);
            LDSM4(b[0][0], b[0][1], b[1][0], b[1][1], bad + kso);
            LDSM4(b[2][0], b[2][1], b[3][0], b[3][1], bad + 16 * SWH * 2 + kso);
            #pragma unroll
            for (int mi = 0; mi < 2; mi++)
                #pragma unroll
                for (int nj = 0; nj < 4; nj++)
                    asm volatile(
                        "mma.sync.aligned.m16n8k16.row.col.f32.f16.f16.f32 "
                        "{%0,%1,%2,%3}, {%4,%5,%6,%7}, {%8,%9}, {%0,%1,%2,%3};"
                        : "+f"(c[mi][nj][0]), "+f"(c[mi][nj][1]),
                          "+f"(c[mi][nj][2]), "+f"(c[mi][nj][3])
                        : "r"(a[mi][0]), "r"(a[mi][1]), "r"(a[mi][2]), "r"(a[mi][3]),
                          "r"(b[nj][0]), "r"(b[nj][1]));
        }
        s = (s + 1 == 3) ? 0 : s + 1;
    }
#undef LOAD_A_STAGE
#undef LOAD_B_STAGE

    GRID_LAUNCH_DEP();

    const bool single = (gridDim.z == 1);
    const bool addb = (blockIdx.z == 0);
    const bool h16 = (flags & 1);
    #pragma unroll
    for (int mi = 0; mi < 2; mi++) {
        const int row = m0 + wm * 32 + mi * 16 + lrow;
        #pragma unroll
        for (int nj = 0; nj < 4; nj++) {
            const int col = n0 + wn * 32 + nj * 8 + 2 * lcol;
            float b0 = addb ? bias[col] : 0.0f;
            float b1 = addb ? bias[col + 1] : 0.0f;
            if (single) {
                if (h16) {
                    __half* Ch = (__half*)C;
                    *(__half2*)(Ch + (size_t)row * ldc + col) =
                        __floats2half2_rn(c[mi][nj][0] + b0, c[mi][nj][1] + b1);
                    *(__half2*)(Ch + (size_t)(row + 8) * ldc + col) =
                        __floats2half2_rn(c[mi][nj][2] + b0, c[mi][nj][3] + b1);
                } else {
                    *(float2*)&C[(size_t)row * ldc + col] =
                        make_float2(c[mi][nj][0] + b0, c[mi][nj][1] + b1);
                    *(float2*)&C[(size_t)(row + 8) * ldc + col] =
                        make_float2(c[mi][nj][2] + b0, c[mi][nj][3] + b1);
                }
            } else {
                atomicAdd(&C[(size_t)row * ldc + col],           c[mi][nj][0] + b0);
                atomicAdd(&C[(size_t)row * ldc + col + 1],       c[mi][nj][1] + b1);
                atomicAdd(&C[(size_t)(row + 8) * ldc + col],     c[mi][nj][2] + b0);
                atomicAdd(&C[(size_t)(row + 8) * ldc + col + 1], c[mi][nj][3] + b1);
            }
        }
    }
}

// ---------------- merged one-time prep ----------------
#define PJ0 512
#define PJ1 1024
#define PJ2 7168
#define PJ3 11264
#define PJ4 15360
#define PJ5 19456
#define PJ6 20480
#define PJ7 21504
#define PJ8 21520
#define PJ9 22032
#define PJTOT 38416

__global__ __launch_bounds__(256) void prep_all(
    const float* __restrict__ att_W, const float* __restrict__ dhp_W,
    const float* __restrict__ W_ih1, const float* __restrict__ W_hh1,
    const float* __restrict__ W_ih2, const float* __restrict__ W_hh2,
    const float* __restrict__ lt_W,
    const float* __restrict__ b_ih1, const float* __restrict__ b_hh1,
    const float* __restrict__ b_ih2, const float* __restrict__ b_hh2,
    const float* __restrict__ lt_b,
    const float* __restrict__ h1_0, const float* __restrict__ c1_0,
    const float* __restrict__ h2_0, const float* __restrict__ c2_0,
    const float* __restrict__ enc_hiddens)
{
    __shared__ float tile[32][33];
    const int bid = blockIdx.x;
    const int tid = threadIdx.x;
    const int tx = tid & 31, ty = tid >> 5;

#define DO_TR(src, K, N, dst, ldd, koff, tIdx) do {                                \
        int nkb = (K) >> 5;                                                        \
        int kb = ((tIdx) % nkb) * 32, nb = ((tIdx) / nkb) * 32;                    \
        _Pragma("unroll")                                                          \
        for (int i = ty; i < 32; i += 8)                                           \
            tile[i][tx] = (src)[(size_t)(kb + i) * (N) + nb + tx];                 \
        __syncthreads();                                                           \
        _Pragma("unroll")                                                          \
        for (int i = ty; i < 32; i += 8)                                           \
            (dst)[(size_t)(nb + i) * (ldd) + (koff) + kb + tx] =                   \
                __float2half_rn(tile[tx][i]);                                      \
    } while (0)

    if (bid < PJ0) {
        DO_TR(att_W, HEz, APz, g_attWt, HEz, 0, bid);
    } else if (bid < PJ1) {
        DO_TR(dhp_W, HDz, APz, g_dhpWt, HDz, 0, bid - PJ0);
    } else if (bid < PJ2) {
        DO_TR(W_ih1, 1536, 4 * HDz, g_W1t, K1z, 0, bid - PJ1);
    } else if (bid < PJ3) {
        DO_TR(W_hh1, HDz, 4 * HDz, g_W1t, K1z, 1536, bid - PJ2);
    } else if (bid < PJ4) {
        DO_TR(W_ih2, HDz, 4 * HDz, g_W2c, K2z, 0, bid - PJ3);
    } else if (bid < PJ5) {
        DO_TR(W_hh2, HDz, 4 * HDz, g_W2c, K2z, 1024, bid - PJ4);
    } else if (bid < PJ6) {
        DO_TR(lt_W, HDz, HDz, g_W2c + (size_t)4 * HDz * K2z, K2z, 0, bid - PJ5);
    } else if (bid < PJ7) {
        int row = 4 * HDz + (bid - PJ6);
        __half z = __float2half(0.0f);
        #pragma unroll
        for (int j = 0; j < 4; j++)
            g_W2c[(size_t)row * K2z + 1024 + tid * 4 + j] = z;
    } else if (bid < PJ8) {
        int i = (bid - PJ7) * 256 + tid;
        g_gb1[i]  = b_ih1[i] + b_hh1[i];
        g_gb2c[i] = b_ih2[i] + b_hh2[i];
        if (i < HDz) g_gb2c[4 * HDz + i] = lt_b[i];
    } else if (bid < PJ9) {
        int idx = (bid - PJ8) * 256 + tid;
        int b = idx >> 10, j = idx & (HDz - 1);
        g_c1[idx] = c1_0[idx];
        g_c2[idx] = c2_0[idx];
        g_abuf1[(size_t)b * K1z + 1536 + j] = __float2half_rn(h1_0[idx]);
        g_abuf2[(size_t)b * K2z + 1024 + j] = __float2half_rn(h2_0[idx]);
        g_hprev[idx] = __float2half_rn(1.0f / (float)HEz);
        #pragma unroll
        for (int gi = 0; gi < 4; gi++)
            g_gates1[(size_t)b * 4 * HDz + gi * HDz + j] = 0.0f;
        if (idx < Bz * APz) g_q[idx] = 0.0f;
    } else {
        size_t i = (size_t)(bid - PJ9) * 256 + tid;
        float4 v = *(const float4*)(enc_hiddens + i * 4);
        __half2* d = (__half2*)g_ehtf;
        d[2 * i]     = __floats2half2_rn(v.x, v.y);
        d[2 * i + 1] = __floats2half2_rn(v.z, v.w);
    }
#undef DO_TR
}

// ---------------- fused attention (PDL, occupancy-tuned) ----------------
__global__ __launch_bounds__(512, 2) void attn_fused(
    const int* __restrict__ enc_masks,
    const float* __restrict__ corr_w, const float* __restrict__ corr_b,
    const float* __restrict__ captions, int t)
{
    __shared__ __align__(16) float qv[APz];
    __shared__ __align__(16) float cw[APz];
    __shared__ float al[Lz];
    const int b = blockIdx.x;
    const int tid = threadIdx.x, lane = tid & 31, warp = tid >> 5;

    if (tid < APz) {
        cw[tid] = corr_w[tid];
        g_abuf1[(size_t)b * K1z + tid] = __float2half_rn(captions[((size_t)t * Bz + b) * Ez + tid]);
    }
    GRID_WAIT();
    if (tid < APz) qv[tid] = g_q[b * APz + tid];
    __syncthreads();

    const float cb = corr_b[0];
    #pragma unroll 2
    for (int li = 0; li < 8; li++) {
        const int l = warp + li * 16;
        const uint4* ep = (const uint4*)(g_enc_proj + ((size_t)(b * Lz + l)) * APz);
        float acc = 0.0f;
        #pragma unroll
        for (int u = 0; u < 2; u++) {
            uint4 pk = ep[lane * 2 + u];
            const __half2* h2 = (const __half2*)&pk;
            const int ap0 = lane * 16 + u * 8;
            #pragma unroll
            for (int p = 0; p < 4; p++) {
                float2 v = __half22float2(h2[p]);
                acc += fast_tanh(v.x + qv[ap0 + 2 * p]) * cw[ap0 + 2 * p];
                acc += fast_tanh(v.y + qv[ap0 + 2 * p + 1]) * cw[ap0 + 2 * p + 1];
            }
        }
        #pragma unroll
        for (int off = 16; off; off >>= 1) acc += __shfl_xor_sync(0xffffffffu, acc, off);
        if (lane == 0) {
            float v = acc + cb;
            if (enc_masks[b * Lz + l]) v = -INFINITY;
            al[l] = v;
        }
    }
    __syncthreads();

    if (tid < 32) {
        float m = -INFINITY;
        #pragma unroll
        for (int i = 0; i < 4; i++) m = fmaxf(m, al[tid + 32 * i]);
        #pragma unroll
        for (int off = 16; off; off >>= 1) m = fmaxf(m, __shfl_xor_sync(0xffffffffu, m, off));
        float ex[4], s = 0.0f;
        #pragma unroll
        for (int i = 0; i < 4; i++) { ex[i] = __expf(al[tid + 32 * i] - m); s += ex[i]; }
        #pragma unroll
        for (int off = 16; off; off >>= 1) s += __shfl_xor_sync(0xffffffffu, s, off);
        float inv = 1.0f / s;
        #pragma unroll
        for (int i = 0; i < 4; i++) al[tid + 32 * i] = ex[i] * inv;
    }
    __syncthreads();
    GRID_LAUNCH_DEP();

    const __half2* eh2 = (const __half2*)(g_ehtf + (size_t)b * Lz * HEz);
    float2 acc2 = make_float2(0.0f, 0.0f);
    #pragma unroll 8
    for (int l = 0; l < Lz; l++) {
        float2 v = __half22float2(eh2[(size_t)l * (HEz / 2) + tid]);
        float a = al[l];
        acc2.x += a * v.x;
        acc2.y += a * v.y;
    }
    *(__half2*)(g_abuf1 + (size_t)b * K1z + Ez + 2 * tid) = __floats2half2_rn(acc2.x, acc2.y);
}

// ---------------- LSTM pointwise (PDL) ----------------
__global__ __launch_bounds__(256) void lstm_point1()
{
    GRID_WAIT();
    int idx = blockIdx.x * blockDim.x + threadIdx.x;
    int b = idx >> 10, j = idx & (HDz - 1);
    const float* g = g_gates1 + (size_t)b * 4 * HDz;
    float ig = sigmoidf_(g[j]);
    float fg = sigmoidf_(g[HDz + j]);
    float gg = tanhf(g[2 * HDz + j]);
    float og = sigmoidf_(g[3 * HDz + j]);
    float cn = fg * g_c1[idx] + ig * gg;
    float hn = og * tanhf(cn);
    GRID_LAUNCH_DEP();
    g_c1[idx] = cn;
    __half hn_h = __float2half_rn(hn);
    g_abuf2[(size_t)b * K2z + j] = hn_h;
    g_abuf1[(size_t)b * K1z + 1536 + j] = hn_h;
    #pragma unroll
    for (int gi = 0; gi < 5; gi++)
        g_g2c[(size_t)b * N2z + gi * HDz + j] = 0.0f;
}

__global__ __launch_bounds__(256) void lstm_point2(float* __restrict__ out)
{
    GRID_WAIT();
    int idx = blockIdx.x * blockDim.x + threadIdx.x;
    int b = idx >> 10, j = idx & (HDz - 1);
    const float* g = g_g2c + (size_t)b * N2z;
    float ig = sigmoidf_(g[j]);
    float fg = sigmoidf_(g[HDz + j]);
    float gg = tanhf(g[2 * HDz + j]);
    float og = sigmoidf_(g[3 * HDz + j]);
    float cn = fg * g_c2[idx] + ig * gg;
    float hn = og * tanhf(cn);
    GRID_LAUNCH_DEP();
    g_c2[idx] = cn;
    __half hn_h = __float2half_rn(hn);
    g_abuf2[(size_t)b * K2z + 1024 + j] = hn_h;
    g_hprev[idx] = hn_h;
    out[idx] = tanhf(g[4 * HDz + j]);
    #pragma unroll
    for (int gi = 0; gi < 4; gi++)
        g_gates1[(size_t)b * 4 * HDz + gi * HDz + j] = 0.0f;
    if (idx < Bz * APz) g_q[idx] = 0.0f;
}

// ---------------- PDL launch helper ----------------
template <class T> struct idt { using type = T; };
template <typename... Args>
static inline void launch_pdl(dim3 grid, dim3 block, size_t shm,
                              void (*kern)(Args...),
                              typename idt<Args>::type... args)
{
    cudaLaunchConfig_t cfg = {};
    cfg.gridDim = grid; cfg.blockDim = block;
    cfg.dynamicSmemBytes = shm; cfg.stream = 0;
    cudaLaunchAttribute at[1];
    at[0].id = cudaLaunchAttributeProgrammaticStreamSerialization;
    at[0].val.programmaticStreamSerializationAllowed = 1;
    cfg.attrs = at; cfg.numAttrs = 1;
    cudaLaunchKernelEx(&cfg, kern, args...);
}

// ---------------- host launcher ----------------
extern "C" void kernel_launch(void* const* d_in, const int* in_sizes, int n_in,
                              void* d_out, int out_size)
{
    const float* enc_hiddens = (const float*)d_in[0];
    const int*   enc_masks   = (const int*)  d_in[1];
    const float* h1_0 = (const float*)d_in[2];
    const float* c1_0 = (const float*)d_in[3];
    const float* h2_0 = (const float*)d_in[4];
    const float* c2_0 = (const float*)d_in[5];
    const float* captions = (const float*)d_in[6];
    const float* att_W = (const float*)d_in[7];
    const float* att_b = (const float*)d_in[8];
    const float* dhp_W = (const float*)d_in[9];
    const float* dhp_b = (const float*)d_in[10];
    const float* corr_w = (const float*)d_in[11];
    const float* corr_b = (const float*)d_in[12];
    const float* lt_W = (const float*)d_in[13];
    const float* lt_b = (const float*)d_in[14];
    const float* W_ih1 = (const float*)d_in[15];
    const float* W_hh1 = (const float*)d_in[16];
    const float* b_ih1 = (const float*)d_in[17];
    const float* b_hh1 = (const float*)d_in[18];
    const float* W_ih2 = (const float*)d_in[19];
    const float* W_hh2 = (const float*)d_in[20];
    const float* b_ih2 = (const float*)d_in[21];
    const float* b_hh2 = (const float*)d_in[22];
    float* out = (float*)d_out;

    static bool inited = false;
    static __half *p_enc_proj, *p_ehtf, *p_a1, *p_a2, *p_hprev;
    static __half *p_W1t, *p_W2c, *p_dhpWt, *p_attWt;
    static float *p_g1, *p_g2c, *p_q, *p_gb1, *p_gb2c;
    if (!inited) {
        cudaGetSymbolAddress((void**)&p_enc_proj, g_enc_proj);
        cudaGetSymbolAddress((void**)&p_ehtf,  g_ehtf);
        cudaGetSymbolAddress((void**)&p_a1,    g_abuf1);
        cudaGetSymbolAddress((void**)&p_a2,    g_abuf2);
        cudaGetSymbolAddress((void**)&p_g1,    g_gates1);
        cudaGetSymbolAddress((void**)&p_g2c,   g_g2c);
        cudaGetSymbolAddress((void**)&p_q,     g_q);
        cudaGetSymbolAddress((void**)&p_hprev, g_hprev);
        cudaGetSymbolAddress((void**)&p_W1t,   g_W1t);
        cudaGetSymbolAddress((void**)&p_W2c,   g_W2c);
        cudaGetSymbolAddress((void**)&p_dhpWt, g_dhpWt);
        cudaGetSymbolAddress((void**)&p_attWt, g_attWt);
        cudaGetSymbolAddress((void**)&p_gb1,   g_gb1);
        cudaGetSymbolAddress((void**)&p_gb2c,  g_gb2c);
        cudaFuncSetAttribute(gemm_mma, cudaFuncAttributeMaxDynamicSharedMemorySize,
                             3 * STGH * 2);
        inited = true;
    }
    const int GSM = 3 * STGH * 2;   // 82944 B

    prep_all<<<PJTOT, 256>>>(att_W, dhp_W, W_ih1, W_hh1, W_ih2, W_hh2, lt_W,
                             b_ih1, b_hh1, b_ih2, b_hh2, lt_b,
                             h1_0, c1_0, h2_0, c2_0, enc_hiddens);

    gemm_mma<<<dim3(APz / BN, Bz * Lz / BMt, 1), 256, GSM>>>(
        p_ehtf, HEz, p_attWt, HEz, (float*)p_enc_proj, APz, HEz, att_b, 1);

    for (int t = 0; t < Tz; t++) {
        // q += hprev @ dhp_W (+dhp_b)   K=1024, z=16
        launch_pdl(dim3(APz / BN, Bz / BMt, 16), dim3(256), (size_t)GSM, gemm_mma,
                   (const __half*)p_hprev, HDz, (const __half*)p_dhpWt, HDz,
                   (float*)p_q, APz, 64, (const float*)dhp_b, 0);

        launch_pdl(dim3(Bz), dim3(512), (size_t)0, attn_fused,
                   enc_masks, corr_w, corr_b, captions, t);

        // gates1 += [x|a|h1] @ W1t^T (+gb1)   K=2560, z=4 -> 256 blocks
        launch_pdl(dim3(4 * HDz / BN, Bz / BMt, 4), dim3(256), (size_t)GSM, gemm_mma,
                   (const __half*)p_a1, K1z, (const __half*)p_W1t, K1z,
                   (float*)p_g1, 4 * HDz, 640, (const float*)p_gb1, 0);

        launch_pdl(dim3(Bz * HDz / 256), dim3(256), (size_t)0, lstm_point1);

        // [gates2 | outsc] += [h1|h2] @ W2c^T (+gb2c)   K=2048, z=4
        launch_pdl(dim3(N2z / BN, Bz / BMt, 4), dim3(256), (size_t)GSM, gemm_mma,
                   (const __half*)p_a2, K2z, (const __half*)p_W2c, K2z,
                   (float*)p_g2c, N2z, 512, (const float*)p_gb2c, 0);

        launch_pdl(dim3(Bz * HDz / 256), dim3(256), (size_t)0, lstm_point2,
                   (float*)(out + (size_t)t * Bz * HDz));
    }
    (void)in_sizes; (void)n_in; (void)out_size;
}

// round 14
// speedup vs baseline: 1.1267x; 1.0782x over previous
#include <cuda_runtime.h>
#include <cuda_fp16.h>
#include <math.h>
#include <cstdint>

#define Bz 128
#define Lz 128
#define HEz 1024
#define HDz 1024
#define Ez 512
#define APz 512
#define Tz 64
#define K1z 2560        // [x_t | a_t | h1_prev]
#define K2z 2048        // [h1 | h2]
#define N2z 5120        // gates2 (4096) + out-proj (1024)

// ---------------- device scratch ----------------
__device__ __align__(128) __half g_enc_proj[Bz * Lz * APz];
__device__ __align__(128) __half g_ehtf[Bz * Lz * HEz];
__device__ __align__(128) float  g_q[Bz * APz];
__device__ __align__(128) float  g_e[Bz * Lz];
__device__ int g_sync[Bz];
__device__ __align__(128) __half g_abuf1[Bz * K1z];
__device__ __align__(128) __half g_abuf2[Bz * K2z];
__device__ __align__(128) float  g_gates1[Bz * 4 * HDz];
__device__ __align__(128) float  g_g2c[Bz * N2z];
__device__ __align__(128) float  g_c1[Bz * HDz];
__device__ __align__(128) float  g_c2[Bz * HDz];
__device__ __align__(128) __half g_hprev[Bz * HDz];
__device__ __align__(128) __half g_W1t[4 * HDz * K1z];
__device__ __align__(128) __half g_W2c[N2z * K2z];
__device__ __align__(128) __half g_dhpWt[APz * HDz];
__device__ __align__(128) __half g_attWt[APz * HEz];
__device__ __align__(128) float  g_gb1[4 * HDz];
__device__ __align__(128) float  g_gb2c[N2z];

__device__ __forceinline__ float fast_tanh(float x) {
    float y; asm("tanh.approx.f32 %0, %1;" : "=f"(y) : "f"(x)); return y;
}
__device__ __forceinline__ float sigmoidf_(float x) { return 1.0f / (1.0f + expf(-x)); }
__device__ __forceinline__ uint32_t smem_u32(const void* p) {
    uint32_t a;
    asm("{ .reg .u64 t; cvta.to.shared.u64 t, %1; cvt.u32.u64 %0, t; }" : "=r"(a) : "l"(p));
    return a;
}
#define CP16(dst, src) \
    asm volatile("cp.async.cg.shared.global [%0], [%1], 16;" :: "r"(dst), "l"(src))
#define LDSM4(d0, d1, d2, d3, addr) \
    asm volatile("ldmatrix.sync.aligned.m8n8.x4.shared.b16 {%0,%1,%2,%3}, [%4];" \
                 : "=r"(d0), "=r"(d1), "=r"(d2), "=r"(d3) : "r"(addr))
// PDL
#define GRID_WAIT()       asm volatile("griddepcontrol.wait;" ::: "memory")
#define GRID_LAUNCH_DEP() asm volatile("griddepcontrol.launch_dependents;" ::: "memory")

// ---------------- 3-stage pipelined HMMA fp16 GEMM (m16n8k16 + ldmatrix + PDL) --
#define BMt 64
#define BN 128
#define BKh 64
#define SWH 72
#define STGH ((BMt + BN) * SWH)

__global__ __launch_bounds__(256, 2) void gemm_mma(
    const __half* __restrict__ A, int lda,
    const __half* __restrict__ Bt, int ldb,
    float* __restrict__ C, int ldc,
    int chunk, const float* __restrict__ bias, int flags)
{
    extern __shared__ __half smh[];
    const int tid = threadIdx.x;
    const int wid = tid >> 5, lane = tid & 31;
    const int wm = wid & 1, wn = wid >> 1;
    const int lrow = lane >> 2, lcol = lane & 3;
    const int n0 = blockIdx.x * BN;
    const int m0 = blockIdx.y * BMt;
    const int kbeg = blockIdx.z * chunk;
    const int NC = chunk / BKh;

    float c[2][4][4];
    #pragma unroll
    for (int i = 0; i < 2; i++)
        #pragma unroll
        for (int j = 0; j < 4; j++)
            #pragma unroll
            for (int r = 0; r < 4; r++) c[i][j][r] = 0.0f;

    const uint32_t sbase = smem_u32(smh);
    const __half* Abase = A + (size_t)m0 * lda + kbeg;
    const __half* Bbase = Bt + (size_t)n0 * ldb + kbeg;

    const int ar0 = (tid + 0)   >> 3, ao0 = (tid + 0)   & 7;
    const int ar1 = (tid + 256) >> 3, ao1 = (tid + 256) & 7;

    const uint32_t a_off =
        ((uint32_t)((wm * 32 + (lane & 15)) * SWH + ((lane >> 4) << 3))) * 2;
    const uint32_t b_off =
        ((uint32_t)((BMt + wn * 32 + (lane & 7) + (((lane >> 4) & 1) << 3)) * SWH
                    + (((lane >> 3) & 1) << 3))) * 2;

#define LOAD_A_STAGE(ck, st) do {                                                 \
        uint32_t sb = sbase + (uint32_t)(st) * STGH * 2;                          \
        const __half* Ag = Abase + (size_t)(ck) * BKh;                            \
        CP16(sb + ar0 * 144 + ao0 * 16, Ag + (size_t)ar0 * lda + ao0 * 8);        \
        CP16(sb + ar1 * 144 + ao1 * 16, Ag + (size_t)ar1 * lda + ao1 * 8);        \
    } while (0)
#define LOAD_B_STAGE(ck, st) do {                                                 \
        uint32_t sb = sbase + (uint32_t)(st) * STGH * 2;                          \
        const __half* Bg = Bbase + (size_t)(ck) * BKh;                            \
        _Pragma("unroll")                                                         \
        for (int j = 0; j < 4; j++) {                                             \
            int i = tid + j * 256;                                                \
            int row = i >> 3, off = i & 7;                                        \
            CP16(sb + (BMt + row) * 144 + off * 16,                               \
                 Bg + (size_t)row * ldb + off * 8);                               \
        }                                                                         \
    } while (0)

    // weight prefetch (independent of predecessor) BEFORE the PDL wait
    LOAD_B_STAGE(0, 0);
    if (NC > 1) LOAD_B_STAGE(1, 1);
    GRID_WAIT();
    LOAD_A_STAGE(0, 0);
    asm volatile("cp.async.commit_group;" ::: "memory");
    if (NC > 1) {
        LOAD_A_STAGE(1, 1);
        asm volatile("cp.async.commit_group;" ::: "memory");
    }

    int s = 0;
    for (int cc = 0; cc < NC; cc++) {
        if (cc + 1 < NC) { asm volatile("cp.async.wait_group 1;" ::: "memory"); }
        else             { asm volatile("cp.async.wait_group 0;" ::: "memory"); }
        __syncthreads();
        if (cc + 2 < NC) {
            int st = s + 2 >= 3 ? s - 1 : s + 2;
            LOAD_B_STAGE(cc + 2, st);
            LOAD_A_STAGE(cc + 2, st);
            asm volatile("cp.async.commit_group;" ::: "memory");
        }

        const uint32_t stg = sbase + (uint32_t)s * STGH * 2;
        const uint32_t aad = stg + a_off;
        const uint32_t bad = stg + b_off;

        #pragma unroll
        for (int ks = 0; ks < 4; ks++) {
            uint32_t a[2][4], b[4][2];
            const uint32_t kso = ks * 32;
            LDSM4(a[0][0], a[0][1], a[0][2], a[0][3], aad + kso);
            LDSM4(a[1][0], a[1][1], a[1][2], a[1][3], aad + 16 * SWH * 2 + kso);
            LDSM4(b[0][0], b[0][1], b[1][0], b[1][1], bad + kso);
            LDSM4(b[2][0], b[2][1], b[3][0], b[3][1], bad + 16 * SWH * 2 + kso);
            #pragma unroll
            for (int mi = 0; mi < 2; mi++)
                #pragma unroll
                for (int nj = 0; nj < 4; nj++)
                    asm volatile(
                        "mma.sync.aligned.m16n8k16.row.col.f32.f16.f16.f32 "
                        "{%0,%1,%2,%3}, {%4,%5,%6,%7}, {%8,%9}, {%0,%1,%2,%3};"
                        : "+f"(c[mi][nj][0]), "+f"(c[mi][nj][1]),
                          "+f"(c[mi][nj][2]), "+f"(c[mi][nj][3])
                        : "r"(a[mi][0]), "r"(a[mi][1]), "r"(a[mi][2]), "r"(a[mi][3]),
                          "r"(b[nj][0]), "r"(b[nj][1]));
        }
        s = (s + 1 == 3) ? 0 : s + 1;
    }
#undef LOAD_A_STAGE
#undef LOAD_B_STAGE

    GRID_LAUNCH_DEP();

    const bool single = (gridDim.z == 1);
    const bool addb = (blockIdx.z == 0);
    const bool h16 = (flags & 1);
    #pragma unroll
    for (int mi = 0; mi < 2; mi++) {
        const int row = m0 + wm * 32 + mi * 16 + lrow;
        #pragma unroll
        for (int nj = 0; nj < 4; nj++) {
            const int col = n0 + wn * 32 + nj * 8 + 2 * lcol;
            float b0 = addb ? bias[col] : 0.0f;
            float b1 = addb ? bias[col + 1] : 0.0f;
            if (single) {
                if (h16) {
                    __half* Ch = (__half*)C;
                    *(__half2*)(Ch + (size_t)row * ldc + col) =
                        __floats2half2_rn(c[mi][nj][0] + b0, c[mi][nj][1] + b1);
                    *(__half2*)(Ch + (size_t)(row + 8) * ldc + col) =
                        __floats2half2_rn(c[mi][nj][2] + b0, c[mi][nj][3] + b1);
                } else {
                    *(float2*)&C[(size_t)row * ldc + col] =
                        make_float2(c[mi][nj][0] + b0, c[mi][nj][1] + b1);
                    *(float2*)&C[(size_t)(row + 8) * ldc + col] =
                        make_float2(c[mi][nj][2] + b0, c[mi][nj][3] + b1);
                }
            } else {
                atomicAdd(&C[(size_t)row * ldc + col],           c[mi][nj][0] + b0);
                atomicAdd(&C[(size_t)row * ldc + col + 1],       c[mi][nj][1] + b1);
                atomicAdd(&C[(size_t)(row + 8) * ldc + col],     c[mi][nj][2] + b0);
                atomicAdd(&C[(size_t)(row + 8) * ldc + col + 1], c[mi][nj][3] + b1);
            }
        }
    }
}

// ---------------- merged one-time prep ----------------
#define PJ0 512
#define PJ1 1024
#define PJ2 7168
#define PJ3 11264
#define PJ4 15360
#define PJ5 19456
#define PJ6 20480
#define PJ7 21504
#define PJ8 21520
#define PJ9 22032
#define PJTOT 38416

__global__ __launch_bounds__(256) void prep_all(
    const float* __restrict__ att_W, const float* __restrict__ dhp_W,
    const float* __restrict__ W_ih1, const float* __restrict__ W_hh1,
    const float* __restrict__ W_ih2, const float* __restrict__ W_hh2,
    const float* __restrict__ lt_W,
    const float* __restrict__ b_ih1, const float* __restrict__ b_hh1,
    const float* __restrict__ b_ih2, const float* __restrict__ b_hh2,
    const float* __restrict__ lt_b,
    const float* __restrict__ h1_0, const float* __restrict__ c1_0,
    const float* __restrict__ h2_0, const float* __restrict__ c2_0,
    const float* __restrict__ enc_hiddens)
{
    __shared__ float tile[32][33];
    const int bid = blockIdx.x;
    const int tid = threadIdx.x;
    const int tx = tid & 31, ty = tid >> 5;

#define DO_TR(src, K, N, dst, ldd, koff, tIdx) do {                                \
        int nkb = (K) >> 5;                                                        \
        int kb = ((tIdx) % nkb) * 32, nb = ((tIdx) / nkb) * 32;                    \
        _Pragma("unroll")                                                          \
        for (int i = ty; i < 32; i += 8)                                           \
            tile[i][tx] = (src)[(size_t)(kb + i) * (N) + nb + tx];                 \
        __syncthreads();                                                           \
        _Pragma("unroll")                                                          \
        for (int i = ty; i < 32; i += 8)                                           \
            (dst)[(size_t)(nb + i) * (ldd) + (koff) + kb + tx] =                   \
                __float2half_rn(tile[tx][i]);                                      \
    } while (0)

    if (bid < PJ0) {
        DO_TR(att_W, HEz, APz, g_attWt, HEz, 0, bid);
    } else if (bid < PJ1) {
        DO_TR(dhp_W, HDz, APz, g_dhpWt, HDz, 0, bid - PJ0);
    } else if (bid < PJ2) {
        DO_TR(W_ih1, 1536, 4 * HDz, g_W1t, K1z, 0, bid - PJ1);
    } else if (bid < PJ3) {
        DO_TR(W_hh1, HDz, 4 * HDz, g_W1t, K1z, 1536, bid - PJ2);
    } else if (bid < PJ4) {
        DO_TR(W_ih2, HDz, 4 * HDz, g_W2c, K2z, 0, bid - PJ3);
    } else if (bid < PJ5) {
        DO_TR(W_hh2, HDz, 4 * HDz, g_W2c, K2z, 1024, bid - PJ4);
    } else if (bid < PJ6) {
        DO_TR(lt_W, HDz, HDz, g_W2c + (size_t)4 * HDz * K2z, K2z, 0, bid - PJ5);
    } else if (bid < PJ7) {
        int row = 4 * HDz + (bid - PJ6);
        __half z = __float2half(0.0f);
        #pragma unroll
        for (int j = 0; j < 4; j++)
            g_W2c[(size_t)row * K2z + 1024 + tid * 4 + j] = z;
    } else if (bid < PJ8) {
        int i = (bid - PJ7) * 256 + tid;
        g_gb1[i]  = b_ih1[i] + b_hh1[i];
        g_gb2c[i] = b_ih2[i] + b_hh2[i];
        if (i < HDz) g_gb2c[4 * HDz + i] = lt_b[i];
        if (i < Bz)  g_sync[i] = 0;
    } else if (bid < PJ9) {
        int idx = (bid - PJ8) * 256 + tid;
        int b = idx >> 10, j = idx & (HDz - 1);
        g_c1[idx] = c1_0[idx];
        g_c2[idx] = c2_0[idx];
        g_abuf1[(size_t)b * K1z + 1536 + j] = __float2half_rn(h1_0[idx]);
        g_abuf2[(size_t)b * K2z + 1024 + j] = __float2half_rn(h2_0[idx]);
        g_hprev[idx] = __float2half_rn(1.0f / (float)HEz);
        #pragma unroll
        for (int gi = 0; gi < 4; gi++)
            g_gates1[(size_t)b * 4 * HDz + gi * HDz + j] = 0.0f;
        if (idx < Bz * APz) g_q[idx] = 0.0f;
    } else {
        size_t i = (size_t)(bid - PJ9) * 256 + tid;
        float4 v = *(const float4*)(enc_hiddens + i * 4);
        __half2* d = (__half2*)g_ehtf;
        d[2 * i]     = __floats2half2_rn(v.x, v.y);
        d[2 * i + 1] = __floats2half2_rn(v.z, v.w);
    }
#undef DO_TR
}

// ---------------- attention, 4-way split with in-kernel sync (PDL) --------------
// grid (Bz, 4) x 256 threads, <=64 regs -> 4 blocks/SM -> 592 slots >= 512 blocks
__global__ __launch_bounds__(256, 4) void attn_split(
    const int* __restrict__ enc_masks,
    const float* __restrict__ corr_w, const float* __restrict__ corr_b,
    const float* __restrict__ captions, int t)
{
    __shared__ __align__(16) float qv[APz];
    __shared__ __align__(16) float cw[APz];
    __shared__ float al[Lz];
    __shared__ float red[128][2];
    const int b = blockIdx.x, y = blockIdx.y;
    const int tid = threadIdx.x, lane = tid & 31, warp = tid >> 5;

    // pre-wait work (independent of predecessor)
    for (int i = tid; i < APz; i += 256) cw[i] = corr_w[i];
    if (tid < 128) {
        int ci = y * 128 + tid;
        g_abuf1[(size_t)b * K1z + ci] =
            __float2half_rn(captions[((size_t)t * Bz + b) * Ez + ci]);
    }
    GRID_WAIT();
    for (int i = tid; i < APz; i += 256) qv[i] = g_q[b * APz + i];
    __syncthreads();

    // phase 1: logits for this block's 32 l's (8 warps x 4 l)
    const float cb = corr_b[0];
    #pragma unroll
    for (int li = 0; li < 4; li++) {
        const int l = y * 32 + warp * 4 + li;
        const uint4* ep = (const uint4*)(g_enc_proj + ((size_t)(b * Lz + l)) * APz);
        float acc = 0.0f;
        #pragma unroll
        for (int u = 0; u < 2; u++) {
            uint4 pk = ep[lane * 2 + u];
            const __half2* h2 = (const __half2*)&pk;
            const int ap0 = lane * 16 + u * 8;
            #pragma unroll
            for (int p = 0; p < 4; p++) {
                float2 v = __half22float2(h2[p]);
                acc += fast_tanh(v.x + qv[ap0 + 2 * p]) * cw[ap0 + 2 * p];
                acc += fast_tanh(v.y + qv[ap0 + 2 * p + 1]) * cw[ap0 + 2 * p + 1];
            }
        }
        #pragma unroll
        for (int off = 16; off; off >>= 1) acc += __shfl_xor_sync(0xffffffffu, acc, off);
        if (lane == 0) {
            float v = acc + cb;
            if (enc_masks[b * Lz + l]) v = -INFINITY;
            g_e[b * Lz + l] = v;
        }
    }

    // cross-block sync among the 4 blocks of this b (monotonic counter)
    __threadfence();
    __syncthreads();
    if (tid == 0) {
        atomicAdd(&g_sync[b], 1);
        const int target = 4 * t + 4;
        while (((volatile int*)g_sync)[b] < target) {}
    }
    __syncthreads();
    __threadfence();

    // softmax over all 128 logits (local per block)
    if (tid < Lz) al[tid] = g_e[b * Lz + tid];
    __syncthreads();
    if (tid < 32) {
        float m = -INFINITY;
        #pragma unroll
        for (int i = 0; i < 4; i++) m = fmaxf(m, al[tid + 32 * i]);
        #pragma unroll
        for (int off = 16; off; off >>= 1) m = fmaxf(m, __shfl_xor_sync(0xffffffffu, m, off));
        float ex[4], s = 0.0f;
        #pragma unroll
        for (int i = 0; i < 4; i++) { ex[i] = __expf(al[tid + 32 * i] - m); s += ex[i]; }
        #pragma unroll
        for (int off = 16; off; off >>= 1) s += __shfl_xor_sync(0xffffffffu, s, off);
        float inv = 1.0f / s;
        #pragma unroll
        for (int i = 0; i < 4; i++) al[tid + 32 * i] = ex[i] * inv;
    }
    __syncthreads();
    GRID_LAUNCH_DEP();

    // phase 2: a_t for this block's 128 half2 columns, 2-way l-split
    const int half = tid >> 7, col = tid & 127;
    const int h2i = y * 128 + col;
    const __half2* eh2 = (const __half2*)(g_ehtf + (size_t)b * Lz * HEz);
    float2 acc2 = make_float2(0.0f, 0.0f);
    const int l0 = half * 64;
    #pragma unroll 8
    for (int l = l0; l < l0 + 64; l++) {
        float2 v = __half22float2(eh2[(size_t)l * (HEz / 2) + h2i]);
        float a = al[l];
        acc2.x += a * v.x;
        acc2.y += a * v.y;
    }
    if (half) { red[col][0] = acc2.x; red[col][1] = acc2.y; }
    __syncthreads();
    if (!half) {
        acc2.x += red[col][0];
        acc2.y += red[col][1];
        *(__half2*)(g_abuf1 + (size_t)b * K1z + Ez + 2 * h2i) =
            __floats2half2_rn(acc2.x, acc2.y);
    }
}

// ---------------- LSTM pointwise (PDL) ----------------
__global__ __launch_bounds__(256) void lstm_point1()
{
    GRID_WAIT();
    int idx = blockIdx.x * blockDim.x + threadIdx.x;
    int b = idx >> 10, j = idx & (HDz - 1);
    const float* g = g_gates1 + (size_t)b * 4 * HDz;
    float ig = sigmoidf_(g[j]);
    float fg = sigmoidf_(g[HDz + j]);
    float gg = tanhf(g[2 * HDz + j]);
    float og = sigmoidf_(g[3 * HDz + j]);
    float cn = fg * g_c1[idx] + ig * gg;
    float hn = og * tanhf(cn);
    GRID_LAUNCH_DEP();
    g_c1[idx] = cn;
    __half hn_h = __float2half_rn(hn);
    g_abuf2[(size_t)b * K2z + j] = hn_h;
    g_abuf1[(size_t)b * K1z + 1536 + j] = hn_h;
    #pragma unroll
    for (int gi = 0; gi < 5; gi++)
        g_g2c[(size_t)b * N2z + gi * HDz + j] = 0.0f;
}

__global__ __launch_bounds__(256) void lstm_point2(float* __restrict__ out)
{
    GRID_WAIT();
    int idx = blockIdx.x * blockDim.x + threadIdx.x;
    int b = idx >> 10, j = idx & (HDz - 1);
    const float* g = g_g2c + (size_t)b * N2z;
    float ig = sigmoidf_(g[j]);
    float fg = sigmoidf_(g[HDz + j]);
    float gg = tanhf(g[2 * HDz + j]);
    float og = sigmoidf_(g[3 * HDz + j]);
    float cn = fg * g_c2[idx] + ig * gg;
    float hn = og * tanhf(cn);
    GRID_LAUNCH_DEP();
    g_c2[idx] = cn;
    __half hn_h = __float2half_rn(hn);
    g_abuf2[(size_t)b * K2z + 1024 + j] = hn_h;
    g_hprev[idx] = hn_h;
    out[idx] = tanhf(g[4 * HDz + j]);
    #pragma unroll
    for (int gi = 0; gi < 4; gi++)
        g_gates1[(size_t)b * 4 * HDz + gi * HDz + j] = 0.0f;
    if (idx < Bz * APz) g_q[idx] = 0.0f;
}

// ---------------- PDL launch helper ----------------
template <class T> struct idt { using type = T; };
template <typename... Args>
static inline void launch_pdl(dim3 grid, dim3 block, size_t shm,
                              void (*kern)(Args...),
                              typename idt<Args>::type... args)
{
    cudaLaunchConfig_t cfg = {};
    cfg.gridDim = grid; cfg.blockDim = block;
    cfg.dynamicSmemBytes = shm; cfg.stream = 0;
    cudaLaunchAttribute at[1];
    at[0].id = cudaLaunchAttributeProgrammaticStreamSerialization;
    at[0].val.programmaticStreamSerializationAllowed = 1;
    cfg.attrs = at; cfg.numAttrs = 1;
    cudaLaunchKernelEx(&cfg, kern, args...);
}

// ---------------- host launcher ----------------
extern "C" void kernel_launch(void* const* d_in, const int* in_sizes, int n_in,
                              void* d_out, int out_size)
{
    const float* enc_hiddens = (const float*)d_in[0];
    const int*   enc_masks   = (const int*)  d_in[1];
    const float* h1_0 = (const float*)d_in[2];
    const float* c1_0 = (const float*)d_in[3];
    const float* h2_0 = (const float*)d_in[4];
    const float* c2_0 = (const float*)d_in[5];
    const float* captions = (const float*)d_in[6];
    const float* att_W = (const float*)d_in[7];
    const float* att_b = (const float*)d_in[8];
    const float* dhp_W = (const float*)d_in[9];
    const float* dhp_b = (const float*)d_in[10];
    const float* corr_w = (const float*)d_in[11];
    const float* corr_b = (const float*)d_in[12];
    const float* lt_W = (const float*)d_in[13];
    const float* lt_b = (const float*)d_in[14];
    const float* W_ih1 = (const float*)d_in[15];
    const float* W_hh1 = (const float*)d_in[16];
    const float* b_ih1 = (const float*)d_in[17];
    const float* b_hh1 = (const float*)d_in[18];
    const float* W_ih2 = (const float*)d_in[19];
    const float* W_hh2 = (const float*)d_in[20];
    const float* b_ih2 = (const float*)d_in[21];
    const float* b_hh2 = (const float*)d_in[22];
    float* out = (float*)d_out;

    static bool inited = false;
    static __half *p_enc_proj, *p_ehtf, *p_a1, *p_a2, *p_hprev;
    static __half *p_W1t, *p_W2c, *p_dhpWt, *p_attWt;
    static float *p_g1, *p_g2c, *p_q, *p_gb1, *p_gb2c;
    if (!inited) {
        cudaGetSymbolAddress((void**)&p_enc_proj, g_enc_proj);
        cudaGetSymbolAddress((void**)&p_ehtf,  g_ehtf);
        cudaGetSymbolAddress((void**)&p_a1,    g_abuf1);
        cudaGetSymbolAddress((void**)&p_a2,    g_abuf2);
        cudaGetSymbolAddress((void**)&p_g1,    g_gates1);
        cudaGetSymbolAddress((void**)&p_g2c,   g_g2c);
        cudaGetSymbolAddress((void**)&p_q,     g_q);
        cudaGetSymbolAddress((void**)&p_hprev, g_hprev);
        cudaGetSymbolAddress((void**)&p_W1t,   g_W1t);
        cudaGetSymbolAddress((void**)&p_W2c,   g_W2c);
        cudaGetSymbolAddress((void**)&p_dhpWt, g_dhpWt);
        cudaGetSymbolAddress((void**)&p_attWt, g_attWt);
        cudaGetSymbolAddress((void**)&p_gb1,   g_gb1);
        cudaGetSymbolAddress((void**)&p_gb2c,  g_gb2c);
        cudaFuncSetAttribute(gemm_mma, cudaFuncAttributeMaxDynamicSharedMemorySize,
                             3 * STGH * 2);
        inited = true;
    }
    const int GSM = 3 * STGH * 2;   // 82944 B

    prep_all<<<PJTOT, 256>>>(att_W, dhp_W, W_ih1, W_hh1, W_ih2, W_hh2, lt_W,
                             b_ih1, b_hh1, b_ih2, b_hh2, lt_b,
                             h1_0, c1_0, h2_0, c2_0, enc_hiddens);

    gemm_mma<<<dim3(APz / BN, Bz * Lz / BMt, 1), 256, GSM>>>(
        p_ehtf, HEz, p_attWt, HEz, (float*)p_enc_proj, APz, HEz, att_b, 1);

    for (int t = 0; t < Tz; t++) {
        // q += hprev @ dhp_W (+dhp_b)   K=1024, z=16
        launch_pdl(dim3(APz / BN, Bz / BMt, 16), dim3(256), (size_t)GSM, gemm_mma,
                   (const __half*)p_hprev, HDz, (const __half*)p_dhpWt, HDz,
                   (float*)p_q, APz, 64, (const float*)dhp_b, 0);

        launch_pdl(dim3(Bz, 4), dim3(256), (size_t)0, attn_split,
                   enc_masks, corr_w, corr_b, captions, t);

        // gates1 += [x|a|h1] @ W1t^T (+gb1)   K=2560, z=4 -> 256 blocks
        launch_pdl(dim3(4 * HDz / BN, Bz / BMt, 4), dim3(256), (size_t)GSM, gemm_mma,
                   (const __half*)p_a1, K1z, (const __half*)p_W1t, K1z,
                   (float*)p_g1, 4 * HDz, 640, (const float*)p_gb1, 0);

        launch_pdl(dim3(Bz * HDz / 256), dim3(256), (size_t)0, lstm_point1);

        // [gates2 | outsc] += [h1|h2] @ W2c^T (+gb2c)   K=2048, z=4
        launch_pdl(dim3(N2z / BN, Bz / BMt, 4), dim3(256), (size_t)GSM, gemm_mma,
                   (const __half*)p_a2, K2z, (const __half*)p_W2c, K2z,
                   (float*)p_g2c, N2z, 512, (const float*)p_gb2c, 0);

        launch_pdl(dim3(Bz * HDz / 256), dim3(256), (size_t)0, lstm_point2,
                   (float*)(out + (size_t)t * Bz * HDz));
    }
    (void)in_sizes; (void)n_in; (void)out_size;
}